// round 1
// baseline (speedup 1.0000x reference)
#include <cuda_runtime.h>

// FittedRankOneRNN: x_{t+1} = (1-a)x_t + a*kappa_t*m + a*u_t*wi, x0=0
// => x_t = p_t*m + q_t*wi  (rank-2 state: two scalars per batch)
//    q_{t+1} = 0.8 q_t + 0.2 u_t            (input-only filter)
//    p_{t+1} = 0.8 p_t + 0.2 kappa_t
//    kappa_t = (1/N) sum_i tanh(p_t m_i + q_t wi_i) n_i
//    z_{t-1} = (1/N) sum_i tanh(p_t m_i + q_t wi_i) w_i   (same tanh vector!)
// One tanh-vector + ONE joint reduction (n-dot and w-dot together) per step.

#define TPB 256
#define EPT 4   // elements per thread: 256*4 = N = 1024

__global__ __launch_bounds__(TPB, 2)
void rank1_rnn_kernel(const float* __restrict__ gu,
                      const float* __restrict__ gm,
                      const float* __restrict__ gn,
                      const float* __restrict__ gwi,
                      const float* __restrict__ gw,
                      float* __restrict__ gz,
                      int T)
{
    __shared__ float s_u[1024];          // T = 1000 <= 1024
    __shared__ float s_part[2][16];      // [buf][warp] for n-dot, [buf][8+warp] for w-dot
    const int b    = blockIdx.x;
    const int tid  = threadIdx.x;
    const int lane = tid & 31;
    const int warp = tid >> 5;

    // Stage this batch's input row into smem (coalesced, one-time).
    for (int i = tid; i < T; i += TPB) s_u[i] = gu[b * T + i];

    // Weights live in registers for the whole recurrence (read once, coalesced).
    float rm[EPT], rn[EPT], rwi[EPT], rw[EPT];
#pragma unroll
    for (int e = 0; e < EPT; e++) {
        const int i = tid + e * TPB;
        rm[e]  = gm[i];
        rn[e]  = gn[i];
        rwi[e] = gwi[i];
        rw[e]  = gw[i];
    }
    __syncthreads();

    const float ALPHA = 0.2f;
    const float BETA  = 0.8f;
    const float INV_N = 1.0f / 1024.0f;

    float p = 0.0f;   // recurrent scalar state (per batch, tracked by every thread)
    float q = 0.0f;   // input-filter scalar state
    float* zrow = gz + b * T;
    int buf = 0;

    for (int t = 1; t <= T; t++) {
        // q_t: independent of p -> issues early, off the critical path.
        q = fmaf(BETA, q, ALPHA * s_u[t - 1]);

        float an = 0.0f, aw = 0.0f;
#pragma unroll
        for (int e = 0; e < EPT; e++) {
            const float s = fmaf(p, rm[e], q * rwi[e]);
            const float r = tanhf(s);
            an = fmaf(r, rn[e], an);
            aw = fmaf(r, rw[e], aw);
        }

        // Warp-level butterfly reduction of both accumulators (pipelined pair).
#pragma unroll
        for (int off = 16; off; off >>= 1) {
            an += __shfl_xor_sync(0xffffffffu, an, off);
            aw += __shfl_xor_sync(0xffffffffu, aw, off);
        }
        if (lane == 0) {
            s_part[buf][warp]     = an;
            s_part[buf][8 + warp] = aw;
        }
        __syncthreads();   // single barrier per step (double-buffered partials)

        // Every thread redundantly finishes the reduction -> no broadcast phase.
        float kap = 0.0f, zz = 0.0f;
#pragma unroll
        for (int wp = 0; wp < 8; wp++) {
            kap += s_part[buf][wp];
            zz  += s_part[buf][8 + wp];
        }
        if (tid == 0) zrow[t - 1] = zz * INV_N;   // fire-and-forget store
        p = fmaf(BETA, p, ALPHA * (kap * INV_N));
        buf ^= 1;
    }
}

extern "C" void kernel_launch(void* const* d_in, const int* in_sizes, int n_in,
                              void* d_out, int out_size)
{
    const float* u  = (const float*)d_in[0];
    const float* m  = (const float*)d_in[1];
    const float* n  = (const float*)d_in[2];
    const float* wi = (const float*)d_in[3];
    const float* w  = (const float*)d_in[4];
    float* z = (float*)d_out;

    const int T = 1000;
    const int B = out_size / T;   // 256
    rank1_rnn_kernel<<<B, TPB>>>(u, m, n, wi, w, z, T);
}